// round 1
// baseline (speedup 1.0000x reference)
#include <cuda_runtime.h>
#include <cuda_bf16.h>
#include <math.h>

// ---------------- problem constants ----------------
#define BB 2
#define SS 1024
#define HH 4096
#define NQ 32
#define NKV 8
#define DD 128
#define II 11008
#define TT (BB*SS)          // 2048 tokens
#define EPS 1e-5f

// ---------------- scratch (device globals, no allocation) ----------------
__device__ float g_hin [TT*HH];        // rmsnorm out (reused for m_in)
__device__ float g_q   [TT*NQ*DD];
__device__ float g_k   [TT*NKV*DD];
__device__ float g_v   [TT*NKV*DD];
__device__ float g_attn[TT*NQ*DD];
__device__ float g_h   [TT*HH];        // residual after attention
__device__ float g_gate[TT*II];
__device__ float g_up  [TT*II];

// ---------------- rmsnorm ----------------
__global__ void rmsnorm_kernel(const float* __restrict__ x,
                               const float* __restrict__ w,
                               float* __restrict__ out) {
    int row = blockIdx.x;
    const float* xr = x + (long)row * HH;
    float ss = 0.f;
    for (int i = threadIdx.x; i < HH; i += blockDim.x) {
        float v = xr[i];
        ss = fmaf(v, v, ss);
    }
    // block reduce
    __shared__ float red[32];
    int lane = threadIdx.x & 31, warp = threadIdx.x >> 5;
    #pragma unroll
    for (int off = 16; off; off >>= 1) ss += __shfl_xor_sync(~0u, ss, off);
    if (lane == 0) red[warp] = ss;
    __syncthreads();
    int nwarp = blockDim.x >> 5;
    if (warp == 0) {
        float v = (lane < nwarp) ? red[lane] : 0.f;
        #pragma unroll
        for (int off = 16; off; off >>= 1) v += __shfl_xor_sync(~0u, v, off);
        if (lane == 0) red[0] = v;
    }
    __syncthreads();
    float inv = rsqrtf(red[0] / (float)HH + EPS);
    float* orow = out + (long)row * HH;
    for (int i = threadIdx.x; i < HH; i += blockDim.x)
        orow[i] = xr[i] * inv * w[i];
}

// ---------------- SGEMM: C[M,N] = A[M,K] @ B[K,N] (+ optional residual) ----
// 128x128 block tile, BK=8, 256 threads, 8x8 per thread.
// Requires M%128==0, N%128==0, K%8==0 (true for all calls here).
template<int EPI>  // 0 = none, 1 = C = res + acc
__global__ void sgemm_kernel(const float* __restrict__ A,
                             const float* __restrict__ B,
                             const float* __restrict__ res,
                             float* __restrict__ C,
                             int M, int N, int K) {
    __shared__ float As[8][128];
    __shared__ float Bs[8][128];
    int tid = threadIdx.x;
    int tx = tid & 15, ty = tid >> 4;
    int row0 = blockIdx.y * 128;
    int col0 = blockIdx.x * 128;

    float acc[8][8];
    #pragma unroll
    for (int i = 0; i < 8; i++)
        #pragma unroll
        for (int j = 0; j < 8; j++) acc[i][j] = 0.f;

    int arow = tid >> 1;
    int ak   = (tid & 1) * 4;
    int brow = tid >> 5;
    int bcol = (tid & 31) * 4;

    const float* Aptr = A + (long)(row0 + arow) * K + ak;
    const float* Bptr = B + (long)brow * N + col0 + bcol;

    for (int k0 = 0; k0 < K; k0 += 8) {
        float4 av = *(const float4*)(Aptr + k0);
        As[ak+0][arow] = av.x; As[ak+1][arow] = av.y;
        As[ak+2][arow] = av.z; As[ak+3][arow] = av.w;
        float4 bv = *(const float4*)(Bptr + (long)k0 * N);
        *(float4*)&Bs[brow][bcol] = bv;
        __syncthreads();
        #pragma unroll
        for (int kk = 0; kk < 8; kk++) {
            float4 a0 = *(const float4*)&As[kk][ty*8];
            float4 a1 = *(const float4*)&As[kk][ty*8+4];
            float4 b0 = *(const float4*)&Bs[kk][tx*8];
            float4 b1 = *(const float4*)&Bs[kk][tx*8+4];
            float a[8] = {a0.x,a0.y,a0.z,a0.w,a1.x,a1.y,a1.z,a1.w};
            float b[8] = {b0.x,b0.y,b0.z,b0.w,b1.x,b1.y,b1.z,b1.w};
            #pragma unroll
            for (int i = 0; i < 8; i++)
                #pragma unroll
                for (int j = 0; j < 8; j++)
                    acc[i][j] = fmaf(a[i], b[j], acc[i][j]);
        }
        __syncthreads();
    }

    #pragma unroll
    for (int i = 0; i < 8; i++) {
        long base = (long)(row0 + ty*8 + i) * N + col0 + tx*8;
        #pragma unroll
        for (int j = 0; j < 8; j += 4) {
            float4 v;
            v.x = acc[i][j]; v.y = acc[i][j+1]; v.z = acc[i][j+2]; v.w = acc[i][j+3];
            if (EPI == 1) {
                float4 rv = *(const float4*)(res + base + j);
                v.x += rv.x; v.y += rv.y; v.z += rv.z; v.w += rv.w;
            }
            *(float4*)(C + base + j) = v;
        }
    }
}

// ---------------- RoPE (in place on q and k) ----------------
__global__ void rope_kernel(float* __restrict__ q, float* __restrict__ k,
                            const float* __restrict__ cosT,
                            const float* __restrict__ sinT) {
    int idx = blockIdx.x * blockDim.x + threadIdx.x;
    // total = TT * (NQ+NKV) * 64
    if (idx >= TT * (NQ + NKV) * 64) return;
    int d  = idx & 63;
    int hh = (idx >> 6) % (NQ + NKV);
    int t  = idx / (64 * (NQ + NKV));
    int s  = t % SS;
    float c1 = cosT[s*DD + d],      s1 = sinT[s*DD + d];
    float c2 = cosT[s*DD + d + 64], s2 = sinT[s*DD + d + 64];
    float* ptr;
    if (hh < NQ) ptr = q + ((long)t*NQ + hh) * DD;
    else         ptr = k + ((long)t*NKV + (hh - NQ)) * DD;
    float x1 = ptr[d], x2 = ptr[d + 64];
    ptr[d]      = x1 * c1 - x2 * s1;
    ptr[d + 64] = x2 * c2 + x1 * s2;
}

// ---------------- causal GQA flash attention (fp32) ----------------
// grid: (S/QPB, NQ, B), block 256 = 8 warps, 1 query per warp.
__global__ void attn_kernel(const float* __restrict__ q,
                            const float* __restrict__ k,
                            const float* __restrict__ v,
                            float* __restrict__ o) {
    constexpr int QPB = 8, TK = 32;
    __shared__ float Ks[TK][DD];
    __shared__ float Vs[TK][DD];
    int b   = blockIdx.z;
    int h   = blockIdx.y;
    int q0  = blockIdx.x * QPB;
    int kvh = h / (NQ / NKV);
    int warp = threadIdx.x >> 5, lane = threadIdx.x & 31;
    int s = q0 + warp;

    const float* qptr = q + ((long)(b*SS + s)*NQ + h) * DD + lane*4;
    float4 qv4 = *(const float4*)qptr;
    float qv[4] = {qv4.x, qv4.y, qv4.z, qv4.w};
    float acc[4] = {0.f, 0.f, 0.f, 0.f};
    float m = -INFINITY, l = 0.f;
    const float scale = 0.08838834764831845f; // 1/sqrt(128)

    int kmax = q0 + QPB - 1;
    for (int k0 = 0; k0 <= kmax; k0 += TK) {
        #pragma unroll
        for (int i = 0; i < 4; i++) {
            int f = i * 1024 + threadIdx.x * 4;
            int r = f >> 7, c = f & 127;
            long gidx = ((long)(b*SS + k0 + r)*NKV + kvh) * DD + c;
            *(float4*)&Ks[r][c] = *(const float4*)(k + gidx);
            *(float4*)&Vs[r][c] = *(const float4*)(v + gidx);
        }
        __syncthreads();
        int kend = min(TK, s - k0 + 1);
        for (int kk = 0; kk < kend; kk++) {
            float4 kk4 = *(const float4*)&Ks[kk][lane*4];
            float p = qv[0]*kk4.x + qv[1]*kk4.y + qv[2]*kk4.z + qv[3]*kk4.w;
            #pragma unroll
            for (int off = 16; off; off >>= 1)
                p += __shfl_xor_sync(~0u, p, off);
            p *= scale;
            float mn = fmaxf(m, p);
            float e = __expf(p - mn);
            float alpha = __expf(m - mn);
            l = l * alpha + e;
            float4 vv = *(const float4*)&Vs[kk][lane*4];
            acc[0] = acc[0]*alpha + e*vv.x;
            acc[1] = acc[1]*alpha + e*vv.y;
            acc[2] = acc[2]*alpha + e*vv.z;
            acc[3] = acc[3]*alpha + e*vv.w;
            m = mn;
        }
        __syncthreads();
    }
    float inv = 1.f / l;
    float* optr = o + ((long)(b*SS + s)*NQ + h) * DD + lane*4;
    float4 ov; ov.x = acc[0]*inv; ov.y = acc[1]*inv; ov.z = acc[2]*inv; ov.w = acc[3]*inv;
    *(float4*)optr = ov;
}

// ---------------- silu(gate) * up (in place on gate) ----------------
__global__ void silu_mul_kernel(float* __restrict__ gate,
                                const float* __restrict__ up, long n) {
    long i = (long)blockIdx.x * blockDim.x + threadIdx.x;
    if (i < n) {
        float g = gate[i];
        float sg = g / (1.f + __expf(-g));
        gate[i] = sg * up[i];
    }
}

// ---------------- launch ----------------
extern "C" void kernel_launch(void* const* d_in, const int* in_sizes, int n_in,
                              void* d_out, int out_size) {
    const float* x      = (const float*)d_in[0];
    const float* cosT   = (const float*)d_in[1];
    const float* sinT   = (const float*)d_in[2];
    const float* anw    = (const float*)d_in[3];
    const float* fnw    = (const float*)d_in[4];
    const float* wq     = (const float*)d_in[5];
    const float* wk     = (const float*)d_in[6];
    const float* wv     = (const float*)d_in[7];
    const float* wo     = (const float*)d_in[8];
    const float* wgate  = (const float*)d_in[9];
    const float* wup    = (const float*)d_in[10];
    const float* wdown  = (const float*)d_in[11];
    float* out = (float*)d_out;

    float *p_hin, *p_q, *p_k, *p_v, *p_attn, *p_h, *p_gate, *p_up;
    cudaGetSymbolAddress((void**)&p_hin,  g_hin);
    cudaGetSymbolAddress((void**)&p_q,    g_q);
    cudaGetSymbolAddress((void**)&p_k,    g_k);
    cudaGetSymbolAddress((void**)&p_v,    g_v);
    cudaGetSymbolAddress((void**)&p_attn, g_attn);
    cudaGetSymbolAddress((void**)&p_h,    g_h);
    cudaGetSymbolAddress((void**)&p_gate, g_gate);
    cudaGetSymbolAddress((void**)&p_up,   g_up);

    // 1) attn rmsnorm
    rmsnorm_kernel<<<TT, 256>>>(x, anw, p_hin);

    // 2) q, k, v projections
    sgemm_kernel<0><<<dim3(NQ*DD/128,  TT/128), 256>>>(p_hin, wq, nullptr, p_q, TT, NQ*DD,  HH);
    sgemm_kernel<0><<<dim3(NKV*DD/128, TT/128), 256>>>(p_hin, wk, nullptr, p_k, TT, NKV*DD, HH);
    sgemm_kernel<0><<<dim3(NKV*DD/128, TT/128), 256>>>(p_hin, wv, nullptr, p_v, TT, NKV*DD, HH);

    // 3) RoPE
    {
        int total = TT * (NQ + NKV) * 64;
        rope_kernel<<<(total + 255) / 256, 256>>>(p_q, p_k, cosT, sinT);
    }

    // 4) attention
    attn_kernel<<<dim3(SS/8, NQ, BB), 256>>>(p_q, p_k, p_v, p_attn);

    // 5) output projection + residual: h = x + attn @ wo
    sgemm_kernel<1><<<dim3(HH/128, TT/128), 256>>>(p_attn, wo, x, p_h, TT, HH, NQ*DD);

    // 6) ffn rmsnorm
    rmsnorm_kernel<<<TT, 256>>>(p_h, fnw, p_hin);

    // 7) gate & up projections
    sgemm_kernel<0><<<dim3(II/128, TT/128), 256>>>(p_hin, wgate, nullptr, p_gate, TT, II, HH);
    sgemm_kernel<0><<<dim3(II/128, TT/128), 256>>>(p_hin, wup,   nullptr, p_up,   TT, II, HH);

    // 8) silu(gate) * up
    {
        long n = (long)TT * II;
        silu_mul_kernel<<<(unsigned)((n + 255) / 256), 256>>>(p_gate, p_up, n);
    }

    // 9) down projection + residual: out = h + mlp @ wdown
    sgemm_kernel<1><<<dim3(HH/128, TT/128), 256>>>(p_gate, wdown, p_h, out, TT, HH, II);
}

// round 3
// speedup vs baseline: 3.2797x; 3.2797x over previous
#include <cuda_runtime.h>
#include <cstdint>
#include <math.h>

// ---------------- problem constants ----------------
#define BB 2
#define SS 1024
#define HH 4096
#define NQ 32
#define NKV 8
#define DD 128
#define II 11008
#define TT (BB*SS)          // 2048 tokens
#define EPS 1e-5f

#define QKV_N (HH + 2*NKV*DD)   // 6144
#define GU_N  (2*II)            // 22016

// ---------------- scratch (device globals, no allocation) ----------------
__device__ float g_hin  [(size_t)TT*HH];
__device__ float g_qkv  [(size_t)TT*QKV_N];
__device__ float g_attn [(size_t)TT*HH];
__device__ float g_h    [(size_t)TT*HH];
__device__ float g_gu   [(size_t)TT*GU_N];
__device__ float g_ffn  [(size_t)TT*II];
__device__ float g_wqkv [(size_t)HH*QKV_N];   // [4096][6144]  (K-major rows)
__device__ float g_wo_r [(size_t)HH*HH];      // [4096][4096]
__device__ float g_wgu  [(size_t)HH*GU_N];    // [4096][22016]
__device__ float g_wd_r [(size_t)II*HH];      // [11008][4096]

// ================= helpers =================
__device__ __forceinline__ float tf32r(float x) {
    uint32_t u;
    asm("cvt.rna.tf32.f32 %0, %1;" : "=r"(u) : "f"(x));
    return __uint_as_float(u);
}
__device__ __forceinline__ uint32_t smem_u32(const void* p) {
    uint32_t a;
    asm("{ .reg .u64 t; cvta.to.shared.u64 t, %1; cvt.u32.u64 %0, t; }" : "=r"(a) : "l"(p));
    return a;
}
__device__ __forceinline__ void cp_async16(uint32_t dst, const void* src) {
    asm volatile("cp.async.cg.shared.global [%0], [%1], 16;" :: "r"(dst), "l"(src));
}
#define CP_COMMIT() asm volatile("cp.async.commit_group;" ::: "memory")
#define CP_WAIT(n)  asm volatile("cp.async.wait_group %0;" :: "n"(n) : "memory")

__device__ __forceinline__ void mma_tf32(float* d, const uint32_t* a, const uint32_t* b) {
    asm volatile(
        "mma.sync.aligned.m16n8k8.row.col.f32.tf32.tf32.f32 "
        "{%0,%1,%2,%3}, {%4,%5,%6,%7}, {%8,%9}, {%0,%1,%2,%3};\n"
        : "+f"(d[0]), "+f"(d[1]), "+f"(d[2]), "+f"(d[3])
        : "r"(a[0]), "r"(a[1]), "r"(a[2]), "r"(a[3]), "r"(b[0]), "r"(b[1]));
}

// ================= tf32 tensor-core GEMM =================
// C[M,N] = A[M,K] @ B[K,N] (+ optional residual).  A,B pre-rounded to tf32.
// CTA tile 128x128, BK=32, 3-stage cp.async pipeline, 8 warps (2m x 4n).
#define BM 128
#define BN 128
#define BK 32
#define STAGES 3
#define ASTRIDE 36          // floats; bank-conflict-free fragment loads
#define BSTRIDE 136
#define STAGE_FLOATS (BM*ASTRIDE + BK*BSTRIDE)   // 4608 + 4352 = 8960
#define SMEM_BYTES (STAGES*STAGE_FLOATS*4)       // 107520

__device__ __forceinline__ void load_stage(uint32_t sb, int st,
                                           const float* __restrict__ A,
                                           const float* __restrict__ B,
                                           int m0, int n0, int k0, int K, int N) {
    int t = threadIdx.x;
    uint32_t sA = sb + st * (STAGE_FLOATS * 4);
    uint32_t sB = sA + BM * ASTRIDE * 4;
    #pragma unroll
    for (int i = 0; i < 4; i++) {                 // A: 128 rows x 32 floats
        int c = t + i * 256;
        int row = c >> 3, off = (c & 7) * 4;
        cp_async16(sA + (uint32_t)(row * ASTRIDE + off) * 4,
                   A + (size_t)(m0 + row) * K + k0 + off);
    }
    #pragma unroll
    for (int i = 0; i < 4; i++) {                 // B: 32 rows x 128 floats
        int c = t + i * 256;
        int row = c >> 5, off = (c & 31) * 4;
        cp_async16(sB + (uint32_t)(row * BSTRIDE + off) * 4,
                   B + (size_t)(k0 + row) * N + n0 + off);
    }
}

template<int EPI>   // 0: C = acc, 1: C = res + acc
__global__ void __launch_bounds__(256, 2)
tc_gemm(const float* __restrict__ A, const float* __restrict__ B,
        const float* __restrict__ res, float* __restrict__ C,
        int M, int N, int K) {
    extern __shared__ float smem[];
    uint32_t sb = smem_u32(smem);
    int tid = threadIdx.x, wid = tid >> 5, lane = tid & 31;
    int wm = wid >> 2, wn = wid & 3;              // 2 x 4 warp grid
    int group = lane >> 2, tig = lane & 3;
    int m0 = blockIdx.x * BM, n0 = blockIdx.y * BN;

    float acc[4][4][4];
    #pragma unroll
    for (int mt = 0; mt < 4; mt++)
        #pragma unroll
        for (int nt = 0; nt < 4; nt++)
            #pragma unroll
            for (int j = 0; j < 4; j++) acc[mt][nt][j] = 0.f;

    int nk = K / BK;
    #pragma unroll
    for (int s = 0; s < STAGES; s++) {
        if (s < nk) load_stage(sb, s, A, B, m0, n0, s * BK, K, N);
        CP_COMMIT();
    }

    for (int kt = 0; kt < nk; kt++) {
        CP_WAIT(STAGES - 1);
        __syncthreads();
        int st = kt % STAGES;
        const float* As = smem + st * STAGE_FLOATS;
        const float* Bs = As + BM * ASTRIDE;

        #pragma unroll
        for (int ks = 0; ks < 4; ks++) {
            int k8 = ks * 8;
            uint32_t afr[4][4];
            uint32_t bfr[4][2];
            #pragma unroll
            for (int mt = 0; mt < 4; mt++) {
                int r = wm * 64 + mt * 16 + group;
                afr[mt][0] = __float_as_uint(As[r * ASTRIDE + k8 + tig]);
                afr[mt][1] = __float_as_uint(As[(r + 8) * ASTRIDE + k8 + tig]);
                afr[mt][2] = __float_as_uint(As[r * ASTRIDE + k8 + tig + 4]);
                afr[mt][3] = __float_as_uint(As[(r + 8) * ASTRIDE + k8 + tig + 4]);
            }
            #pragma unroll
            for (int nt = 0; nt < 4; nt++) {
                int cn = wn * 32 + nt * 8 + group;
                bfr[nt][0] = __float_as_uint(Bs[(k8 + tig) * BSTRIDE + cn]);
                bfr[nt][1] = __float_as_uint(Bs[(k8 + tig + 4) * BSTRIDE + cn]);
            }
            #pragma unroll
            for (int mt = 0; mt < 4; mt++)
                #pragma unroll
                for (int nt = 0; nt < 4; nt++)
                    mma_tf32(acc[mt][nt], afr[mt], bfr[nt]);
        }
        __syncthreads();
        int nxt = kt + STAGES;
        if (nxt < nk) load_stage(sb, st, A, B, m0, n0, nxt * BK, K, N);
        CP_COMMIT();
    }

    // epilogue
    #pragma unroll
    for (int mt = 0; mt < 4; mt++) {
        int r0 = m0 + wm * 64 + mt * 16 + group;
        #pragma unroll
        for (int nt = 0; nt < 4; nt++) {
            int c = n0 + wn * 32 + nt * 8 + 2 * tig;
            size_t i0 = (size_t)r0 * N + c;
            size_t i1 = (size_t)(r0 + 8) * N + c;
            float2 v0 = make_float2(acc[mt][nt][0], acc[mt][nt][1]);
            float2 v1 = make_float2(acc[mt][nt][2], acc[mt][nt][3]);
            if (EPI == 1) {
                float2 r0v = *(const float2*)(res + i0);
                float2 r1v = *(const float2*)(res + i1);
                v0.x += r0v.x; v0.y += r0v.y;
                v1.x += r1v.x; v1.y += r1v.y;
            }
            *(float2*)(C + i0) = v0;
            *(float2*)(C + i1) = v1;
        }
    }
}

// ================= weight pack (tf32 round + optional column offset) ========
__global__ void pack_tf32(const float* __restrict__ W, float* __restrict__ dst,
                          int N, int dstN, long colOff, long total4) {
    long i = (long)blockIdx.x * blockDim.x + threadIdx.x;
    if (i >= total4) return;
    int n4 = N >> 2;
    long row = i / n4;
    int c4 = (int)(i - row * n4);
    float4 v = *(const float4*)(W + row * (long)N + c4 * 4);
    v.x = tf32r(v.x); v.y = tf32r(v.y); v.z = tf32r(v.z); v.w = tf32r(v.w);
    *(float4*)(dst + row * (long)dstN + colOff + c4 * 4) = v;
}

// ================= rmsnorm (tf32-rounded output) =================
__global__ void rmsnorm_kernel(const float* __restrict__ x,
                               const float* __restrict__ w,
                               float* __restrict__ out) {
    int row = blockIdx.x;
    const float* xr = x + (size_t)row * HH;
    float ss = 0.f;
    for (int i = threadIdx.x; i < HH; i += blockDim.x) {
        float v = xr[i];
        ss = fmaf(v, v, ss);
    }
    __shared__ float red[32];
    int lane = threadIdx.x & 31, warp = threadIdx.x >> 5;
    #pragma unroll
    for (int off = 16; off; off >>= 1) ss += __shfl_xor_sync(~0u, ss, off);
    if (lane == 0) red[warp] = ss;
    __syncthreads();
    int nwarp = blockDim.x >> 5;
    if (warp == 0) {
        float v = (lane < nwarp) ? red[lane] : 0.f;
        #pragma unroll
        for (int off = 16; off; off >>= 1) v += __shfl_xor_sync(~0u, v, off);
        if (lane == 0) red[0] = v;
    }
    __syncthreads();
    float inv = rsqrtf(red[0] / (float)HH + EPS);
    float* orow = out + (size_t)row * HH;
    for (int i = threadIdx.x; i < HH; i += blockDim.x)
        orow[i] = tf32r(xr[i] * inv * w[i]);
}

// ================= RoPE (in place on fused qkv) =================
__global__ void rope_kernel(float* __restrict__ qkv,
                            const float* __restrict__ cosT,
                            const float* __restrict__ sinT) {
    int idx = blockIdx.x * blockDim.x + threadIdx.x;
    if (idx >= TT * (NQ + NKV) * 64) return;
    int d  = idx & 63;
    int hh = (idx >> 6) % (NQ + NKV);
    int t  = idx / (64 * (NQ + NKV));
    int s  = t % SS;
    float c1 = cosT[s*DD + d],      s1 = sinT[s*DD + d];
    float c2 = cosT[s*DD + d + 64], s2 = sinT[s*DD + d + 64];
    float* ptr;
    if (hh < NQ) ptr = qkv + (size_t)t * QKV_N + hh * DD;
    else         ptr = qkv + (size_t)t * QKV_N + HH + (hh - NQ) * DD;
    float x1 = ptr[d], x2 = ptr[d + 64];
    ptr[d]      = x1 * c1 - x2 * s1;
    ptr[d + 64] = x2 * c2 + x1 * s2;
}

// ================= causal GQA flash attention (fp32, tf32-rounded out) ======
__global__ void attn_kernel(const float* __restrict__ qkv,
                            float* __restrict__ o) {
    constexpr int QPB = 8, TK = 32;
    __shared__ float Ks[TK][DD];
    __shared__ float Vs[TK][DD];
    int b   = blockIdx.z;
    int h   = blockIdx.y;
    int q0  = blockIdx.x * QPB;
    int kvh = h / (NQ / NKV);
    int warp = threadIdx.x >> 5, lane = threadIdx.x & 31;
    int s = q0 + warp;

    const float* qptr = qkv + (size_t)(b*SS + s) * QKV_N + h * DD + lane * 4;
    float4 qv4 = *(const float4*)qptr;
    float qv[4] = {qv4.x, qv4.y, qv4.z, qv4.w};
    float acc[4] = {0.f, 0.f, 0.f, 0.f};
    float m = -INFINITY, l = 0.f;
    const float scale = 0.08838834764831845f;

    int kmax = q0 + QPB - 1;
    for (int k0 = 0; k0 <= kmax; k0 += TK) {
        #pragma unroll
        for (int i = 0; i < 4; i++) {
            int f = i * 1024 + threadIdx.x * 4;
            int r = f >> 7, c = f & 127;
            size_t gbase = (size_t)(b*SS + k0 + r) * QKV_N + kvh * DD + c;
            *(float4*)&Ks[r][c] = *(const float4*)(qkv + gbase + HH);
            *(float4*)&Vs[r][c] = *(const float4*)(qkv + gbase + HH + NKV*DD);
        }
        __syncthreads();
        int kend = min(TK, s - k0 + 1);
        for (int kk = 0; kk < kend; kk++) {
            float4 kk4 = *(const float4*)&Ks[kk][lane*4];
            float p = qv[0]*kk4.x + qv[1]*kk4.y + qv[2]*kk4.z + qv[3]*kk4.w;
            #pragma unroll
            for (int off = 16; off; off >>= 1)
                p += __shfl_xor_sync(~0u, p, off);
            p *= scale;
            float mn = fmaxf(m, p);
            float e = __expf(p - mn);
            float alpha = __expf(m - mn);
            l = l * alpha + e;
            float4 vv = *(const float4*)&Vs[kk][lane*4];
            acc[0] = acc[0]*alpha + e*vv.x;
            acc[1] = acc[1]*alpha + e*vv.y;
            acc[2] = acc[2]*alpha + e*vv.z;
            acc[3] = acc[3]*alpha + e*vv.w;
            m = mn;
        }
        __syncthreads();
    }
    float inv = 1.f / l;
    float* optr = o + ((size_t)(b*SS + s) * NQ + h) * DD + lane * 4;
    float4 ov;
    ov.x = tf32r(acc[0]*inv); ov.y = tf32r(acc[1]*inv);
    ov.z = tf32r(acc[2]*inv); ov.w = tf32r(acc[3]*inv);
    *(float4*)optr = ov;
}

// ================= silu(gate) * up (tf32-rounded out) =================
__global__ void silu_mul_kernel(const float* __restrict__ gu, float* __restrict__ out) {
    int i = blockIdx.x * blockDim.x + threadIdx.x;   // [0, II)
    int t = blockIdx.y;
    const float* row = gu + (size_t)t * GU_N;
    float g = row[i], u = row[II + i];
    out[(size_t)t * II + i] = tf32r(g / (1.f + __expf(-g)) * u);
}

// ================= launch =================
extern "C" void kernel_launch(void* const* d_in, const int* in_sizes, int n_in,
                              void* d_out, int out_size) {
    const float* x     = (const float*)d_in[0];
    const float* cosT  = (const float*)d_in[1];
    const float* sinT  = (const float*)d_in[2];
    const float* anw   = (const float*)d_in[3];
    const float* fnw   = (const float*)d_in[4];
    const float* wq    = (const float*)d_in[5];
    const float* wk    = (const float*)d_in[6];
    const float* wv    = (const float*)d_in[7];
    const float* wo    = (const float*)d_in[8];
    const float* wgate = (const float*)d_in[9];
    const float* wup   = (const float*)d_in[10];
    const float* wdown = (const float*)d_in[11];
    float* out = (float*)d_out;

    float *p_hin, *p_qkv, *p_attn, *p_h, *p_gu, *p_ffn;
    float *p_wqkv, *p_wo, *p_wgu, *p_wd;
    cudaGetSymbolAddress((void**)&p_hin,  g_hin);
    cudaGetSymbolAddress((void**)&p_qkv,  g_qkv);
    cudaGetSymbolAddress((void**)&p_attn, g_attn);
    cudaGetSymbolAddress((void**)&p_h,    g_h);
    cudaGetSymbolAddress((void**)&p_gu,   g_gu);
    cudaGetSymbolAddress((void**)&p_ffn,  g_ffn);
    cudaGetSymbolAddress((void**)&p_wqkv, g_wqkv);
    cudaGetSymbolAddress((void**)&p_wo,   g_wo_r);
    cudaGetSymbolAddress((void**)&p_wgu,  g_wgu);
    cudaGetSymbolAddress((void**)&p_wd,   g_wd_r);

    cudaFuncSetAttribute(tc_gemm<0>, cudaFuncAttributeMaxDynamicSharedMemorySize, SMEM_BYTES);
    cudaFuncSetAttribute(tc_gemm<1>, cudaFuncAttributeMaxDynamicSharedMemorySize, SMEM_BYTES);

    // weight packs (tf32 rounding + fusion)
    {
        long t4;
        t4 = (long)HH*HH/4;
        pack_tf32<<<(unsigned)((t4+255)/256), 256>>>(wq, p_wqkv, HH, QKV_N, 0, t4);
        t4 = (long)HH*(NKV*DD)/4;
        pack_tf32<<<(unsigned)((t4+255)/256), 256>>>(wk, p_wqkv, NKV*DD, QKV_N, HH, t4);
        pack_tf32<<<(unsigned)((t4+255)/256), 256>>>(wv, p_wqkv, NKV*DD, QKV_N, HH+NKV*DD, t4);
        t4 = (long)HH*HH/4;
        pack_tf32<<<(unsigned)((t4+255)/256), 256>>>(wo, p_wo, HH, HH, 0, t4);
        t4 = (long)HH*II/4;
        pack_tf32<<<(unsigned)((t4+255)/256), 256>>>(wgate, p_wgu, II, GU_N, 0, t4);
        pack_tf32<<<(unsigned)((t4+255)/256), 256>>>(wup,   p_wgu, II, GU_N, II, t4);
        t4 = (long)II*HH/4;
        pack_tf32<<<(unsigned)((t4+255)/256), 256>>>(wdown, p_wd, HH, HH, 0, t4);
    }

    // 1) attn rmsnorm (tf32-rounded)
    rmsnorm_kernel<<<TT, 256>>>(x, anw, p_hin);

    // 2) fused qkv projection: [2048, 6144] = [2048,4096] @ [4096,6144]
    tc_gemm<0><<<dim3(TT/BM, QKV_N/BN), 256, SMEM_BYTES>>>(p_hin, p_wqkv, nullptr, p_qkv, TT, QKV_N, HH);

    // 3) RoPE
    {
        int total = TT * (NQ + NKV) * 64;
        rope_kernel<<<(total + 255) / 256, 256>>>(p_qkv, cosT, sinT);
    }

    // 4) attention
    attn_kernel<<<dim3(SS/8, NQ, BB), 256>>>(p_qkv, p_attn);

    // 5) output projection + residual: h = x + attn @ wo
    tc_gemm<1><<<dim3(TT/BM, HH/BN), 256, SMEM_BYTES>>>(p_attn, p_wo, x, p_h, TT, HH, HH);

    // 6) ffn rmsnorm
    rmsnorm_kernel<<<TT, 256>>>(p_h, fnw, p_hin);

    // 7) fused gate+up: [2048, 22016]
    tc_gemm<0><<<dim3(TT/BM, GU_N/BN), 256, SMEM_BYTES>>>(p_hin, p_wgu, nullptr, p_gu, TT, GU_N, HH);

    // 8) silu(gate) * up
    silu_mul_kernel<<<dim3(II/256, TT), 256>>>(p_gu, p_ffn);

    // 9) down projection + residual: out = h + ffn @ wdown
    tc_gemm<1><<<dim3(TT/BM, HH/BN), 256, SMEM_BYTES>>>(p_ffn, p_wd, p_h, out, TT, HH, II);
}

// round 4
// speedup vs baseline: 4.5143x; 1.3764x over previous
#include <cuda_runtime.h>
#include <cuda_fp16.h>
#include <cstdint>
#include <math.h>

// ---------------- problem constants ----------------
#define BB 2
#define SS 1024
#define HH 4096
#define NQ 32
#define NKV 8
#define DD 128
#define II 11008
#define TT (BB*SS)          // 2048 tokens
#define EPS 1e-5f

#define QKV_N (HH + 2*NKV*DD)   // 6144
#define GU_N  (2*II)            // 22016

// ---------------- scratch (device globals, no allocation) ----------------
__device__ __half g_hin  [(size_t)TT*HH];       // rmsnorm out (half, GEMM A)
__device__ float  g_qkv  [(size_t)TT*QKV_N];
__device__ __half g_attn [(size_t)TT*HH];       // attention out (half, GEMM A)
__device__ float  g_h    [(size_t)TT*HH];
__device__ float  g_gu   [(size_t)TT*GU_N];
__device__ __half g_ffn  [(size_t)TT*II];       // silu*up out (half, GEMM A)
__device__ __half g_wqkv [(size_t)QKV_N*HH];    // Wt[N][K] half
__device__ __half g_wo_t [(size_t)HH*HH];
__device__ __half g_wgu  [(size_t)GU_N*HH];
__device__ __half g_wd_t [(size_t)HH*II];

// ================= helpers =================
__device__ __forceinline__ uint32_t smem_u32(const void* p) {
    uint32_t a;
    asm("{ .reg .u64 t; cvta.to.shared.u64 t, %1; cvt.u32.u64 %0, t; }" : "=r"(a) : "l"(p));
    return a;
}
__device__ __forceinline__ void cp_async16(uint32_t dst, const void* src) {
    asm volatile("cp.async.cg.shared.global [%0], [%1], 16;" :: "r"(dst), "l"(src));
}
#define CP_COMMIT() asm volatile("cp.async.commit_group;" ::: "memory")
#define CP_WAIT(n)  asm volatile("cp.async.wait_group %0;" :: "n"(n) : "memory")

__device__ __forceinline__ void ldsm4(uint32_t addr, uint32_t& r0, uint32_t& r1,
                                      uint32_t& r2, uint32_t& r3) {
    asm volatile("ldmatrix.sync.aligned.m8n8.x4.shared.b16 {%0,%1,%2,%3}, [%4];"
                 : "=r"(r0), "=r"(r1), "=r"(r2), "=r"(r3) : "r"(addr));
}
__device__ __forceinline__ void mma_f16(float* d, const uint32_t* a, const uint32_t* b) {
    asm volatile(
        "mma.sync.aligned.m16n8k16.row.col.f32.f16.f16.f32 "
        "{%0,%1,%2,%3}, {%4,%5,%6,%7}, {%8,%9}, {%0,%1,%2,%3};\n"
        : "+f"(d[0]), "+f"(d[1]), "+f"(d[2]), "+f"(d[3])
        : "r"(a[0]), "r"(a[1]), "r"(a[2]), "r"(a[3]), "r"(b[0]), "r"(b[1]));
}

// ================= fp16 tensor-core GEMM =================
// C[M,N] = A[M,K] @ Bt[N,K]^T (+ optional fp32 residual). A, Bt are half.
// CTA tile 128x128, BK=32, 4-stage cp.async, 8 warps (2m x 4n), warp 64x32.
#define BM 128
#define BN 128
#define BK 32
#define STAGES 4
#define ROWH 40                           // halves per padded row (80 bytes)
#define TILE_BYTES (128*ROWH*2)           // 10240
#define STAGE_B (2*TILE_BYTES)            // 20480
#define SMEM_BYTES (STAGES*STAGE_B)       // 81920

__device__ __forceinline__ void load_stage(uint32_t sb, int st,
                                           const __half* __restrict__ A,
                                           const __half* __restrict__ B,
                                           int m0, int n0, int k0, int K) {
    int t = threadIdx.x;
    uint32_t sA = sb + st * STAGE_B;
    uint32_t sB = sA + TILE_BYTES;
    #pragma unroll
    for (int i = 0; i < 2; i++) {
        int c = t + i * 256;
        int row = c >> 2, ch = c & 3;
        cp_async16(sA + (uint32_t)(row * 80 + ch * 16),
                   A + (size_t)(m0 + row) * K + k0 + ch * 8);
    }
    #pragma unroll
    for (int i = 0; i < 2; i++) {
        int c = t + i * 256;
        int row = c >> 2, ch = c & 3;
        cp_async16(sB + (uint32_t)(row * 80 + ch * 16),
                   B + (size_t)(n0 + row) * K + k0 + ch * 8);
    }
}

template<int EPI>   // 0: C = acc, 1: C = res + acc
__global__ void __launch_bounds__(256, 2)
hgemm(const __half* __restrict__ A, const __half* __restrict__ B,
      const float* __restrict__ res, float* __restrict__ C,
      int M, int N, int K) {
    extern __shared__ char smem[];
    uint32_t sb = smem_u32(smem);
    int tid = threadIdx.x, wid = tid >> 5, lane = tid & 31;
    int wm = wid >> 2, wn = wid & 3;
    int group = lane >> 2, tig = lane & 3;
    int m0 = blockIdx.x * BM, n0 = blockIdx.y * BN;

    int rowoff = (lane & 7) + ((lane >> 3) & 1) * 8;
    int koff   = (lane >> 4) * 16;

    float acc[4][4][4];
    #pragma unroll
    for (int mt = 0; mt < 4; mt++)
        #pragma unroll
        for (int nt = 0; nt < 4; nt++)
            #pragma unroll
            for (int j = 0; j < 4; j++) acc[mt][nt][j] = 0.f;

    int nk = K / BK;
    #pragma unroll
    for (int s = 0; s < STAGES; s++) {
        load_stage(sb, s, A, B, m0, n0, s * BK, K);
        CP_COMMIT();
    }

    for (int kt = 0; kt < nk; kt++) {
        CP_WAIT(STAGES - 1);
        __syncthreads();
        int st = kt & (STAGES - 1);
        uint32_t sA = sb + st * STAGE_B;
        uint32_t sB = sA + TILE_BYTES;

        #pragma unroll
        for (int ks = 0; ks < 2; ks++) {
            uint32_t a[4][4], bfr[4][2];
            #pragma unroll
            for (int mt = 0; mt < 4; mt++) {
                uint32_t ad = sA + (uint32_t)((wm * 64 + mt * 16 + rowoff) * 80 + ks * 32 + koff);
                ldsm4(ad, a[mt][0], a[mt][1], a[mt][2], a[mt][3]);
            }
            #pragma unroll
            for (int np = 0; np < 2; np++) {
                uint32_t bd = sB + (uint32_t)((wn * 32 + np * 16 + rowoff) * 80 + ks * 32 + koff);
                uint32_t r0, r1, r2, r3;
                ldsm4(bd, r0, r1, r2, r3);
                bfr[2*np][0] = r0; bfr[2*np][1] = r2;
                bfr[2*np+1][0] = r1; bfr[2*np+1][1] = r3;
            }
            #pragma unroll
            for (int mt = 0; mt < 4; mt++)
                #pragma unroll
                for (int nt = 0; nt < 4; nt++)
                    mma_f16(acc[mt][nt], a[mt], bfr[nt]);
        }
        __syncthreads();
        int nxt = kt + STAGES;
        if (nxt < nk) load_stage(sb, st, A, B, m0, n0, nxt * BK, K);
        CP_COMMIT();
    }

    // epilogue (fp32 out)
    #pragma unroll
    for (int mt = 0; mt < 4; mt++) {
        int r0 = m0 + wm * 64 + mt * 16 + group;
        #pragma unroll
        for (int nt = 0; nt < 4; nt++) {
            int c = n0 + wn * 32 + nt * 8 + 2 * tig;
            size_t i0 = (size_t)r0 * N + c;
            size_t i1 = (size_t)(r0 + 8) * N + c;
            float2 v0 = make_float2(acc[mt][nt][0], acc[mt][nt][1]);
            float2 v1 = make_float2(acc[mt][nt][2], acc[mt][nt][3]);
            if (EPI == 1) {
                float2 r0v = *(const float2*)(res + i0);
                float2 r1v = *(const float2*)(res + i1);
                v0.x += r0v.x; v0.y += r0v.y;
                v1.x += r1v.x; v1.y += r1v.y;
            }
            *(float2*)(C + i0) = v0;
            *(float2*)(C + i1) = v1;
        }
    }
}

// ================= weight pack: W[K][N] fp32 -> Wt[N][K] half =================
__global__ void pack_h_t(const float* __restrict__ W, __half* __restrict__ Wt,
                         int K, int N) {
    __shared__ float t[32][33];
    int k0 = blockIdx.x * 32, n0 = blockIdx.y * 32;
    int tx = threadIdx.x, ty = threadIdx.y;   // 32 x 8
    #pragma unroll
    for (int i = 0; i < 32; i += 8)
        t[ty + i][tx] = W[(size_t)(k0 + ty + i) * N + n0 + tx];
    __syncthreads();
    #pragma unroll
    for (int i = 0; i < 32; i += 8)
        Wt[(size_t)(n0 + ty + i) * K + k0 + tx] = __float2half_rn(t[tx][ty + i]);
}

// ================= rmsnorm (half output) =================
__global__ void rmsnorm_kernel(const float* __restrict__ x,
                               const float* __restrict__ w,
                               __half* __restrict__ out) {
    int row = blockIdx.x;
    const float* xr = x + (size_t)row * HH;
    float ss = 0.f;
    for (int i = threadIdx.x; i < HH; i += blockDim.x) {
        float v = xr[i];
        ss = fmaf(v, v, ss);
    }
    __shared__ float red[32];
    int lane = threadIdx.x & 31, warp = threadIdx.x >> 5;
    #pragma unroll
    for (int off = 16; off; off >>= 1) ss += __shfl_xor_sync(~0u, ss, off);
    if (lane == 0) red[warp] = ss;
    __syncthreads();
    int nwarp = blockDim.x >> 5;
    if (warp == 0) {
        float v = (lane < nwarp) ? red[lane] : 0.f;
        #pragma unroll
        for (int off = 16; off; off >>= 1) v += __shfl_xor_sync(~0u, v, off);
        if (lane == 0) red[0] = v;
    }
    __syncthreads();
    float inv = rsqrtf(red[0] / (float)HH + EPS);
    __half* orow = out + (size_t)row * HH;
    for (int i = threadIdx.x; i < HH; i += blockDim.x)
        orow[i] = __float2half_rn(xr[i] * inv * w[i]);
}

// ================= RoPE (in place on fused qkv, fp32) =================
__global__ void rope_kernel(float* __restrict__ qkv,
                            const float* __restrict__ cosT,
                            const float* __restrict__ sinT) {
    int idx = blockIdx.x * blockDim.x + threadIdx.x;
    if (idx >= TT * (NQ + NKV) * 64) return;
    int d  = idx & 63;
    int hh = (idx >> 6) % (NQ + NKV);
    int t  = idx / (64 * (NQ + NKV));
    int s  = t % SS;
    float c1 = cosT[s*DD + d],      s1 = sinT[s*DD + d];
    float c2 = cosT[s*DD + d + 64], s2 = sinT[s*DD + d + 64];
    float* ptr;
    if (hh < NQ) ptr = qkv + (size_t)t * QKV_N + hh * DD;
    else         ptr = qkv + (size_t)t * QKV_N + HH + (hh - NQ) * DD;
    float x1 = ptr[d], x2 = ptr[d + 64];
    ptr[d]      = x1 * c1 - x2 * s1;
    ptr[d + 64] = x2 * c2 + x1 * s2;
}

// ================= causal GQA flash attention (fp32, half out) ===============
__global__ void attn_kernel(const float* __restrict__ qkv,
                            __half* __restrict__ o) {
    constexpr int QPB = 8, TK = 32;
    __shared__ float Ks[TK][DD];
    __shared__ float Vs[TK][DD];
    int b   = blockIdx.z;
    int h   = blockIdx.y;
    int q0  = blockIdx.x * QPB;
    int kvh = h / (NQ / NKV);
    int warp = threadIdx.x >> 5, lane = threadIdx.x & 31;
    int s = q0 + warp;

    const float* qptr = qkv + (size_t)(b*SS + s) * QKV_N + h * DD + lane * 4;
    float4 qv4 = *(const float4*)qptr;
    float qv[4] = {qv4.x, qv4.y, qv4.z, qv4.w};
    float acc[4] = {0.f, 0.f, 0.f, 0.f};
    float m = -INFINITY, l = 0.f;
    const float scale = 0.08838834764831845f;

    int kmax = q0 + QPB - 1;
    for (int k0 = 0; k0 <= kmax; k0 += TK) {
        #pragma unroll
        for (int i = 0; i < 4; i++) {
            int f = i * 1024 + threadIdx.x * 4;
            int r = f >> 7, c = f & 127;
            size_t gbase = (size_t)(b*SS + k0 + r) * QKV_N + kvh * DD + c;
            *(float4*)&Ks[r][c] = *(const float4*)(qkv + gbase + HH);
            *(float4*)&Vs[r][c] = *(const float4*)(qkv + gbase + HH + NKV*DD);
        }
        __syncthreads();
        int kend = min(TK, s - k0 + 1);
        for (int kk = 0; kk < kend; kk++) {
            float4 kk4 = *(const float4*)&Ks[kk][lane*4];
            float p = qv[0]*kk4.x + qv[1]*kk4.y + qv[2]*kk4.z + qv[3]*kk4.w;
            #pragma unroll
            for (int off = 16; off; off >>= 1)
                p += __shfl_xor_sync(~0u, p, off);
            p *= scale;
            float mn = fmaxf(m, p);
            float e = __expf(p - mn);
            float alpha = __expf(m - mn);
            l = l * alpha + e;
            float4 vv = *(const float4*)&Vs[kk][lane*4];
            acc[0] = acc[0]*alpha + e*vv.x;
            acc[1] = acc[1]*alpha + e*vv.y;
            acc[2] = acc[2]*alpha + e*vv.z;
            acc[3] = acc[3]*alpha + e*vv.w;
            m = mn;
        }
        __syncthreads();
    }
    float inv = 1.f / l;
    __half* optr = o + ((size_t)(b*SS + s) * NQ + h) * DD + lane * 4;
    __half2 h0 = __floats2half2_rn(acc[0]*inv, acc[1]*inv);
    __half2 h1 = __floats2half2_rn(acc[2]*inv, acc[3]*inv);
    *(__half2*)(optr)     = h0;
    *(__half2*)(optr + 2) = h1;
}

// ================= silu(gate) * up (half out) =================
__global__ void silu_mul_kernel(const float* __restrict__ gu, __half* __restrict__ out) {
    int i = blockIdx.x * blockDim.x + threadIdx.x;   // [0, II)
    int t = blockIdx.y;
    const float* row = gu + (size_t)t * GU_N;
    float g = row[i], u = row[II + i];
    out[(size_t)t * II + i] = __float2half_rn(g / (1.f + __expf(-g)) * u);
}

// ================= launch =================
extern "C" void kernel_launch(void* const* d_in, const int* in_sizes, int n_in,
                              void* d_out, int out_size) {
    const float* x     = (const float*)d_in[0];
    const float* cosT  = (const float*)d_in[1];
    const float* sinT  = (const float*)d_in[2];
    const float* anw   = (const float*)d_in[3];
    const float* fnw   = (const float*)d_in[4];
    const float* wq    = (const float*)d_in[5];
    const float* wk    = (const float*)d_in[6];
    const float* wv    = (const float*)d_in[7];
    const float* wo    = (const float*)d_in[8];
    const float* wgate = (const float*)d_in[9];
    const float* wup   = (const float*)d_in[10];
    const float* wdown = (const float*)d_in[11];
    float* out = (float*)d_out;

    __half *p_hin, *p_attn, *p_ffn, *p_wqkv, *p_wo, *p_wgu, *p_wd;
    float *p_qkv, *p_h, *p_gu;
    cudaGetSymbolAddress((void**)&p_hin,  g_hin);
    cudaGetSymbolAddress((void**)&p_qkv,  g_qkv);
    cudaGetSymbolAddress((void**)&p_attn, g_attn);
    cudaGetSymbolAddress((void**)&p_h,    g_h);
    cudaGetSymbolAddress((void**)&p_gu,   g_gu);
    cudaGetSymbolAddress((void**)&p_ffn,  g_ffn);
    cudaGetSymbolAddress((void**)&p_wqkv, g_wqkv);
    cudaGetSymbolAddress((void**)&p_wo,   g_wo_t);
    cudaGetSymbolAddress((void**)&p_wgu,  g_wgu);
    cudaGetSymbolAddress((void**)&p_wd,   g_wd_t);

    cudaFuncSetAttribute(hgemm<0>, cudaFuncAttributeMaxDynamicSharedMemorySize, SMEM_BYTES);
    cudaFuncSetAttribute(hgemm<1>, cudaFuncAttributeMaxDynamicSharedMemorySize, SMEM_BYTES);

    dim3 tb(32, 8);
    // weight packs: fp32 [K][N] -> half [N][K] (transposed, fused)
    pack_h_t<<<dim3(HH/32, HH/32), tb>>>(wq, p_wqkv, HH, HH);
    pack_h_t<<<dim3(HH/32, (NKV*DD)/32), tb>>>(wk, p_wqkv + (size_t)HH*HH, HH, NKV*DD);
    pack_h_t<<<dim3(HH/32, (NKV*DD)/32), tb>>>(wv, p_wqkv + (size_t)(HH+NKV*DD)*HH, HH, NKV*DD);
    pack_h_t<<<dim3(HH/32, HH/32), tb>>>(wo, p_wo, HH, HH);
    pack_h_t<<<dim3(HH/32, II/32), tb>>>(wgate, p_wgu, HH, II);
    pack_h_t<<<dim3(HH/32, II/32), tb>>>(wup,   p_wgu + (size_t)II*HH, HH, II);
    pack_h_t<<<dim3(II/32, HH/32), tb>>>(wdown, p_wd, II, HH);

    // 1) attn rmsnorm -> half
    rmsnorm_kernel<<<TT, 256>>>(x, anw, p_hin);

    // 2) fused qkv projection: [2048, 6144]
    hgemm<0><<<dim3(TT/BM, QKV_N/BN), 256, SMEM_BYTES>>>(p_hin, p_wqkv, nullptr, p_qkv, TT, QKV_N, HH);

    // 3) RoPE
    {
        int total = TT * (NQ + NKV) * 64;
        rope_kernel<<<(total + 255) / 256, 256>>>(p_qkv, cosT, sinT);
    }

    // 4) attention -> half
    attn_kernel<<<dim3(SS/8, NQ, BB), 256>>>(p_qkv, p_attn);

    // 5) output projection + residual: h = x + attn @ wo
    hgemm<1><<<dim3(TT/BM, HH/BN), 256, SMEM_BYTES>>>(p_attn, p_wo, x, p_h, TT, HH, HH);

    // 6) ffn rmsnorm -> half
    rmsnorm_kernel<<<TT, 256>>>(p_h, fnw, p_hin);

    // 7) fused gate+up: [2048, 22016]
    hgemm<0><<<dim3(TT/BM, GU_N/BN), 256, SMEM_BYTES>>>(p_hin, p_wgu, nullptr, p_gu, TT, GU_N, HH);

    // 8) silu(gate) * up -> half
    silu_mul_kernel<<<dim3(II/256, TT), 256>>>(p_gu, p_ffn);

    // 9) down projection + residual: out = h + ffn @ wdown
    hgemm<1><<<dim3(TT/BM, HH/BN), 256, SMEM_BYTES>>>(p_ffn, p_wd, p_h, out, TT, HH, II);
}

// round 5
// speedup vs baseline: 6.9320x; 1.5356x over previous
#include <cuda_runtime.h>
#include <cuda_fp16.h>
#include <cstdint>
#include <math.h>

// ---------------- problem constants ----------------
#define BB 2
#define SS 1024
#define HH 4096
#define NQ 32
#define NKV 8
#define DD 128
#define II 11008
#define TT (BB*SS)          // 2048 tokens
#define EPS 1e-5f

#define QKV_N (HH + 2*NKV*DD)   // 6144
#define GU_N  (2*II)            // 22016

// ---------------- scratch (device globals, no allocation) ----------------
__device__ __half g_hin  [(size_t)TT*HH];       // rmsnorm out (half, GEMM A)
__device__ float  g_qkv  [(size_t)TT*QKV_N];
__device__ __half g_qh   [(size_t)TT*NQ*DD];    // roped q (scaled), [b,h,s,d]
__device__ __half g_kh   [(size_t)TT*NKV*DD];   // roped k, [b,kvh,s,d]
__device__ __half g_vt   [(size_t)TT*NKV*DD];   // v^T, [b,kvh,d,s]
__device__ __half g_attn [(size_t)TT*HH];       // attention out (half, GEMM A)
__device__ float  g_h    [(size_t)TT*HH];
__device__ float  g_gu   [(size_t)TT*GU_N];
__device__ __half g_ffn  [(size_t)TT*II];       // silu*up out (half, GEMM A)
__device__ __half g_wqkv [(size_t)QKV_N*HH];    // Wt[N][K] half
__device__ __half g_wo_t [(size_t)HH*HH];
__device__ __half g_wgu  [(size_t)GU_N*HH];
__device__ __half g_wd_t [(size_t)HH*II];

// ================= helpers =================
__device__ __forceinline__ uint32_t smem_u32(const void* p) {
    uint32_t a;
    asm("{ .reg .u64 t; cvta.to.shared.u64 t, %1; cvt.u32.u64 %0, t; }" : "=r"(a) : "l"(p));
    return a;
}
__device__ __forceinline__ void cp_async16(uint32_t dst, const void* src) {
    asm volatile("cp.async.cg.shared.global [%0], [%1], 16;" :: "r"(dst), "l"(src));
}
#define CP_COMMIT() asm volatile("cp.async.commit_group;" ::: "memory")
#define CP_WAIT(n)  asm volatile("cp.async.wait_group %0;" :: "n"(n) : "memory")

__device__ __forceinline__ void ldsm4(uint32_t addr, uint32_t& r0, uint32_t& r1,
                                      uint32_t& r2, uint32_t& r3) {
    asm volatile("ldmatrix.sync.aligned.m8n8.x4.shared.b16 {%0,%1,%2,%3}, [%4];"
                 : "=r"(r0), "=r"(r1), "=r"(r2), "=r"(r3) : "r"(addr));
}
__device__ __forceinline__ void mma_f16(float* d, const uint32_t* a, const uint32_t* b) {
    asm volatile(
        "mma.sync.aligned.m16n8k16.row.col.f32.f16.f16.f32 "
        "{%0,%1,%2,%3}, {%4,%5,%6,%7}, {%8,%9}, {%0,%1,%2,%3};\n"
        : "+f"(d[0]), "+f"(d[1]), "+f"(d[2]), "+f"(d[3])
        : "r"(a[0]), "r"(a[1]), "r"(a[2]), "r"(a[3]), "r"(b[0]), "r"(b[1]));
}
__device__ __forceinline__ uint32_t h2pack(float a, float b) {
    __half2 h = __floats2half2_rn(a, b);
    return *(uint32_t*)&h;
}

// ================= fp16 tensor-core GEMM (unchanged from R4) =================
#define BM 128
#define BN 128
#define BK 32
#define STAGES 4
#define ROWH 40
#define TILE_BYTES (128*ROWH*2)
#define STAGE_B (2*TILE_BYTES)
#define SMEM_BYTES (STAGES*STAGE_B)

__device__ __forceinline__ void load_stage(uint32_t sb, int st,
                                           const __half* __restrict__ A,
                                           const __half* __restrict__ B,
                                           int m0, int n0, int k0, int K) {
    int t = threadIdx.x;
    uint32_t sA = sb + st * STAGE_B;
    uint32_t sB = sA + TILE_BYTES;
    #pragma unroll
    for (int i = 0; i < 2; i++) {
        int c = t + i * 256;
        int row = c >> 2, ch = c & 3;
        cp_async16(sA + (uint32_t)(row * 80 + ch * 16),
                   A + (size_t)(m0 + row) * K + k0 + ch * 8);
    }
    #pragma unroll
    for (int i = 0; i < 2; i++) {
        int c = t + i * 256;
        int row = c >> 2, ch = c & 3;
        cp_async16(sB + (uint32_t)(row * 80 + ch * 16),
                   B + (size_t)(n0 + row) * K + k0 + ch * 8);
    }
}

template<int EPI>
__global__ void __launch_bounds__(256, 2)
hgemm(const __half* __restrict__ A, const __half* __restrict__ B,
      const float* __restrict__ res, float* __restrict__ C,
      int M, int N, int K) {
    extern __shared__ char smem[];
    uint32_t sb = smem_u32(smem);
    int tid = threadIdx.x, wid = tid >> 5, lane = tid & 31;
    int wm = wid >> 2, wn = wid & 3;
    int group = lane >> 2, tig = lane & 3;
    int m0 = blockIdx.x * BM, n0 = blockIdx.y * BN;

    int rowoff = (lane & 7) + ((lane >> 3) & 1) * 8;
    int koff   = (lane >> 4) * 16;

    float acc[4][4][4];
    #pragma unroll
    for (int mt = 0; mt < 4; mt++)
        #pragma unroll
        for (int nt = 0; nt < 4; nt++)
            #pragma unroll
            for (int j = 0; j < 4; j++) acc[mt][nt][j] = 0.f;

    int nk = K / BK;
    #pragma unroll
    for (int s = 0; s < STAGES; s++) {
        load_stage(sb, s, A, B, m0, n0, s * BK, K);
        CP_COMMIT();
    }

    for (int kt = 0; kt < nk; kt++) {
        CP_WAIT(STAGES - 1);
        __syncthreads();
        int st = kt & (STAGES - 1);
        uint32_t sA = sb + st * STAGE_B;
        uint32_t sB = sA + TILE_BYTES;

        #pragma unroll
        for (int ks = 0; ks < 2; ks++) {
            uint32_t a[4][4], bfr[4][2];
            #pragma unroll
            for (int mt = 0; mt < 4; mt++) {
                uint32_t ad = sA + (uint32_t)((wm * 64 + mt * 16 + rowoff) * 80 + ks * 32 + koff);
                ldsm4(ad, a[mt][0], a[mt][1], a[mt][2], a[mt][3]);
            }
            #pragma unroll
            for (int np = 0; np < 2; np++) {
                uint32_t bd = sB + (uint32_t)((wn * 32 + np * 16 + rowoff) * 80 + ks * 32 + koff);
                uint32_t r0, r1, r2, r3;
                ldsm4(bd, r0, r1, r2, r3);
                bfr[2*np][0] = r0; bfr[2*np][1] = r2;
                bfr[2*np+1][0] = r1; bfr[2*np+1][1] = r3;
            }
            #pragma unroll
            for (int mt = 0; mt < 4; mt++)
                #pragma unroll
                for (int nt = 0; nt < 4; nt++)
                    mma_f16(acc[mt][nt], a[mt], bfr[nt]);
        }
        __syncthreads();
        int nxt = kt + STAGES;
        if (nxt < nk) load_stage(sb, st, A, B, m0, n0, nxt * BK, K);
        CP_COMMIT();
    }

    #pragma unroll
    for (int mt = 0; mt < 4; mt++) {
        int r0 = m0 + wm * 64 + mt * 16 + group;
        #pragma unroll
        for (int nt = 0; nt < 4; nt++) {
            int c = n0 + wn * 32 + nt * 8 + 2 * tig;
            size_t i0 = (size_t)r0 * N + c;
            size_t i1 = (size_t)(r0 + 8) * N + c;
            float2 v0 = make_float2(acc[mt][nt][0], acc[mt][nt][1]);
            float2 v1 = make_float2(acc[mt][nt][2], acc[mt][nt][3]);
            if (EPI == 1) {
                float2 r0v = *(const float2*)(res + i0);
                float2 r1v = *(const float2*)(res + i1);
                v0.x += r0v.x; v0.y += r0v.y;
                v1.x += r1v.x; v1.y += r1v.y;
            }
            *(float2*)(C + i0) = v0;
            *(float2*)(C + i1) = v1;
        }
    }
}

// ================= weight pack: W[K][N] fp32 -> Wt[N][K] half =================
__global__ void pack_h_t(const float* __restrict__ W, __half* __restrict__ Wt,
                         int K, int N) {
    __shared__ float t[32][33];
    int k0 = blockIdx.x * 32, n0 = blockIdx.y * 32;
    int tx = threadIdx.x, ty = threadIdx.y;
    #pragma unroll
    for (int i = 0; i < 32; i += 8)
        t[ty + i][tx] = W[(size_t)(k0 + ty + i) * N + n0 + tx];
    __syncthreads();
    #pragma unroll
    for (int i = 0; i < 32; i += 8)
        Wt[(size_t)(n0 + ty + i) * K + k0 + tx] = __float2half_rn(t[tx][ty + i]);
}

// ================= rmsnorm (half output) =================
__global__ void rmsnorm_kernel(const float* __restrict__ x,
                               const float* __restrict__ w,
                               __half* __restrict__ out) {
    int row = blockIdx.x;
    const float* xr = x + (size_t)row * HH;
    float ss = 0.f;
    for (int i = threadIdx.x; i < HH; i += blockDim.x) {
        float v = xr[i];
        ss = fmaf(v, v, ss);
    }
    __shared__ float red[32];
    int lane = threadIdx.x & 31, warp = threadIdx.x >> 5;
    #pragma unroll
    for (int off = 16; off; off >>= 1) ss += __shfl_xor_sync(~0u, ss, off);
    if (lane == 0) red[warp] = ss;
    __syncthreads();
    int nwarp = blockDim.x >> 5;
    if (warp == 0) {
        float v = (lane < nwarp) ? red[lane] : 0.f;
        #pragma unroll
        for (int off = 16; off; off >>= 1) v += __shfl_xor_sync(~0u, v, off);
        if (lane == 0) red[0] = v;
    }
    __syncthreads();
    float inv = rsqrtf(red[0] / (float)HH + EPS);
    __half* orow = out + (size_t)row * HH;
    for (int i = threadIdx.x; i < HH; i += blockDim.x)
        orow[i] = __float2half_rn(xr[i] * inv * w[i]);
}

// ================= RoPE extract: q (scaled) =================
__global__ void rope_q(const float* __restrict__ qkv,
                       const float* __restrict__ cosT,
                       const float* __restrict__ sinT,
                       __half* __restrict__ qh) {
    int idx = blockIdx.x * blockDim.x + threadIdx.x;
    if (idx >= TT * NQ * 64) return;
    const float scale = 0.08838834764831845f;
    int d = idx & 63;
    int h = (idx >> 6) % NQ;
    int t = idx / (64 * NQ);
    int s = t % SS, b = t / SS;
    float c1 = cosT[s*DD + d],      s1 = sinT[s*DD + d];
    float c2 = cosT[s*DD + d + 64], s2 = sinT[s*DD + d + 64];
    const float* p = qkv + (size_t)t * QKV_N + h * DD;
    float x1 = p[d], x2 = p[d + 64];
    size_t row = ((size_t)(b*NQ + h)*SS + s) * DD;
    qh[row + d]      = __float2half_rn((x1 * c1 - x2 * s1) * scale);
    qh[row + d + 64] = __float2half_rn((x2 * c2 + x1 * s2) * scale);
}

// ================= RoPE extract: k =================
__global__ void rope_k(const float* __restrict__ qkv,
                       const float* __restrict__ cosT,
                       const float* __restrict__ sinT,
                       __half* __restrict__ kh) {
    int idx = blockIdx.x * blockDim.x + threadIdx.x;
    if (idx >= TT * NKV * 64) return;
    int d = idx & 63;
    int h = (idx >> 6) % NKV;
    int t = idx / (64 * NKV);
    int s = t % SS, b = t / SS;
    float c1 = cosT[s*DD + d],      s1 = sinT[s*DD + d];
    float c2 = cosT[s*DD + d + 64], s2 = sinT[s*DD + d + 64];
    const float* p = qkv + (size_t)t * QKV_N + HH + h * DD;
    float x1 = p[d], x2 = p[d + 64];
    size_t row = ((size_t)(b*NKV + h)*SS + s) * DD;
    kh[row + d]      = __float2half_rn(x1 * c1 - x2 * s1);
    kh[row + d + 64] = __float2half_rn(x2 * c2 + x1 * s2);
}

// ================= V extract + transpose: vt[b,kvh,d,s] =================
__global__ void v_trans(const float* __restrict__ qkv, __half* __restrict__ vt) {
    __shared__ __half tile[32][33];
    int s0 = blockIdx.x * 32, d0 = blockIdx.y * 32;
    int bk = blockIdx.z;
    int b = bk / NKV, kvh = bk % NKV;
    int tx = threadIdx.x, ty = threadIdx.y;   // 32 x 8
    #pragma unroll
    for (int i = 0; i < 32; i += 8) {
        int s = s0 + ty + i;
        float v = qkv[(size_t)(b*SS + s) * QKV_N + HH + NKV*DD + kvh*DD + d0 + tx];
        tile[ty + i][tx] = __float2half_rn(v);
    }
    __syncthreads();
    #pragma unroll
    for (int i = 0; i < 32; i += 8)
        vt[((size_t)(b*NKV + kvh)*DD + d0 + ty + i) * SS + s0 + tx] = tile[tx][ty + i];
}

// ================= fp16 flash attention =================
// grid (S/64, NQ, B), 128 threads (4 warps, 16 q-rows each), KV tiles of 64.
#define AQT 64
#define AKT 64
#define QSTR 136          // halves per Q/K row (272B, conflict-free ldsm)
#define VSTR 72           // halves per Vt row (144B)
#define AQ_BYTES (AQT*QSTR*2)          // 17408
#define AK_BYTES (AKT*QSTR*2)          // 17408
#define AV_BYTES (DD*VSTR*2)           // 18432
#define ATT_SMEM (AQ_BYTES + 2*AK_BYTES + 2*AV_BYTES)   // 89088

__global__ void __launch_bounds__(128, 2)
fattn(const __half* __restrict__ qh, const __half* __restrict__ kh,
      const __half* __restrict__ vt, __half* __restrict__ o) {
    extern __shared__ char sm[];
    uint32_t sb = smem_u32(sm);
    uint32_t sQ = sb;
    uint32_t sK = sQ + AQ_BYTES;
    uint32_t sV = sK + 2*AK_BYTES;

    int b = blockIdx.z, h = blockIdx.y;
    int qt = gridDim.x - 1 - blockIdx.x;       // longest first
    int kvh = h >> 2;                          // NQ/NKV = 4
    int q0 = qt * AQT;
    int tid = threadIdx.x, w = tid >> 5, lane = tid & 31;
    int g = lane >> 2, tig = lane & 3;
    int rowoff = lane & 15;
    int kofs   = (lane >> 4) * 16;             // bytes

    const __half* qbase = qh + ((size_t)(b*NQ + h)*SS + q0) * DD;
    const __half* kbase = kh + ((size_t)(b*NKV + kvh)*SS) * DD;
    const __half* vbase = vt + ((size_t)(b*NKV + kvh)*DD) * SS;

    // Q tile: 64 x 128 halves = 1024 x 16B
    for (int i = tid; i < 1024; i += 128) {
        int r = i >> 4, c = i & 15;
        cp_async16(sQ + (uint32_t)(r*(QSTR*2) + c*16), qbase + (size_t)r*DD + c*8);
    }
    CP_COMMIT();

    int nt = qt + 1;
    // stage 0 KV
    {
        uint32_t dK = sK, dV = sV;
        for (int i = tid; i < 1024; i += 128) {
            int r = i >> 4, c = i & 15;
            cp_async16(dK + (uint32_t)(r*(QSTR*2) + c*16), kbase + (size_t)r*DD + c*8);
        }
        for (int i = tid; i < 1024; i += 128) {
            int r = i >> 3, c = i & 7;
            cp_async16(dV + (uint32_t)(r*(VSTR*2) + c*16), vbase + (size_t)r*SS + c*8);
        }
    }
    CP_COMMIT();

    // Q fragments (wait for Q group: allow 1 pending = KV0)
    CP_WAIT(1);
    __syncthreads();
    uint32_t qfr[8][4];
    #pragma unroll
    for (int kb = 0; kb < 8; kb++)
        ldsm4(sQ + (uint32_t)((w*16 + rowoff)*(QSTR*2) + kb*32 + kofs),
              qfr[kb][0], qfr[kb][1], qfr[kb][2], qfr[kb][3]);

    float m0v = -INFINITY, m1v = -INFINITY, l0 = 0.f, l1 = 0.f;
    float oac[16][4];
    #pragma unroll
    for (int i = 0; i < 16; i++)
        #pragma unroll
        for (int j = 0; j < 4; j++) oac[i][j] = 0.f;

    for (int t = 0; t < nt; t++) {
        if (t + 1 < nt) {
            uint32_t dK = sK + ((t+1)&1) * AK_BYTES;
            uint32_t dV = sV + ((t+1)&1) * AV_BYTES;
            const __half* kp = kbase + (size_t)(t+1)*AKT*DD;
            const __half* vp = vbase + (t+1)*AKT;
            for (int i = tid; i < 1024; i += 128) {
                int r = i >> 4, c = i & 15;
                cp_async16(dK + (uint32_t)(r*(QSTR*2) + c*16), kp + (size_t)r*DD + c*8);
            }
            for (int i = tid; i < 1024; i += 128) {
                int r = i >> 3, c = i & 7;
                cp_async16(dV + (uint32_t)(r*(VSTR*2) + c*16), vp + (size_t)r*SS + c*8);
            }
        }
        CP_COMMIT();
        CP_WAIT(1);          // stage t ready
        __syncthreads();

        uint32_t cK = sK + (t&1) * AK_BYTES;
        uint32_t cV = sV + (t&1) * AV_BYTES;

        // S = Q @ K^T  (16 x 64 per warp)
        float s[8][4];
        #pragma unroll
        for (int j = 0; j < 8; j++)
            #pragma unroll
            for (int c = 0; c < 4; c++) s[j][c] = 0.f;

        #pragma unroll
        for (int kb = 0; kb < 8; kb++) {
            #pragma unroll
            for (int np = 0; np < 4; np++) {
                uint32_t r0, r1, r2, r3;
                ldsm4(cK + (uint32_t)((16*np + rowoff)*(QSTR*2) + kb*32 + kofs),
                      r0, r1, r2, r3);
                uint32_t b0[2] = {r0, r2}, b1[2] = {r1, r3};
                mma_f16(s[2*np],   qfr[kb], b0);
                mma_f16(s[2*np+1], qfr[kb], b1);
            }
        }

        // causal mask on diagonal tile
        if (t == qt) {
            int r0l = w*16 + g, r1l = r0l + 8;
            #pragma unroll
            for (int j = 0; j < 8; j++) {
                int c0 = 8*j + 2*tig;
                if (c0     > r0l) s[j][0] = -1e30f;
                if (c0 + 1 > r0l) s[j][1] = -1e30f;
                if (c0     > r1l) s[j][2] = -1e30f;
                if (c0 + 1 > r1l) s[j][3] = -1e30f;
            }
        }

        // row max (rows g, g+8)
        float tm0 = -1e30f, tm1 = -1e30f;
        #pragma unroll
        for (int j = 0; j < 8; j++) {
            tm0 = fmaxf(tm0, fmaxf(s[j][0], s[j][1]));
            tm1 = fmaxf(tm1, fmaxf(s[j][2], s[j][3]));
        }
        tm0 = fmaxf(tm0, __shfl_xor_sync(~0u, tm0, 1));
        tm0 = fmaxf(tm0, __shfl_xor_sync(~0u, tm0, 2));
        tm1 = fmaxf(tm1, __shfl_xor_sync(~0u, tm1, 1));
        tm1 = fmaxf(tm1, __shfl_xor_sync(~0u, tm1, 2));

        float mn0 = fmaxf(m0v, tm0), mn1 = fmaxf(m1v, tm1);
        float a0 = __expf(m0v - mn0), a1 = __expf(m1v - mn1);
        m0v = mn0; m1v = mn1;

        float ts0 = 0.f, ts1 = 0.f;
        #pragma unroll
        for (int j = 0; j < 8; j++) {
            s[j][0] = __expf(s[j][0] - mn0);
            s[j][1] = __expf(s[j][1] - mn0);
            s[j][2] = __expf(s[j][2] - mn1);
            s[j][3] = __expf(s[j][3] - mn1);
            ts0 += s[j][0] + s[j][1];
            ts1 += s[j][2] + s[j][3];
        }
        ts0 += __shfl_xor_sync(~0u, ts0, 1);
        ts0 += __shfl_xor_sync(~0u, ts0, 2);
        ts1 += __shfl_xor_sync(~0u, ts1, 1);
        ts1 += __shfl_xor_sync(~0u, ts1, 2);
        l0 = l0 * a0 + ts0;
        l1 = l1 * a1 + ts1;

        // rescale O
        #pragma unroll
        for (int i = 0; i < 16; i++) {
            oac[i][0] *= a0; oac[i][1] *= a0;
            oac[i][2] *= a1; oac[i][3] *= a1;
        }

        // P -> A fragments
        uint32_t pf[4][4];
        #pragma unroll
        for (int jj = 0; jj < 4; jj++) {
            pf[jj][0] = h2pack(s[2*jj][0],   s[2*jj][1]);
            pf[jj][1] = h2pack(s[2*jj][2],   s[2*jj][3]);
            pf[jj][2] = h2pack(s[2*jj+1][0], s[2*jj+1][1]);
            pf[jj][3] = h2pack(s[2*jj+1][2], s[2*jj+1][3]);
        }

        // O += P @ V
        #pragma unroll
        for (int jj = 0; jj < 4; jj++) {
            #pragma unroll
            for (int dp = 0; dp < 8; dp++) {
                uint32_t r0, r1, r2, r3;
                ldsm4(cV + (uint32_t)((16*dp + rowoff)*(VSTR*2) + jj*32 + kofs),
                      r0, r1, r2, r3);
                uint32_t b0[2] = {r0, r2}, b1[2] = {r1, r3};
                mma_f16(oac[2*dp],   pf[jj], b0);
                mma_f16(oac[2*dp+1], pf[jj], b1);
            }
        }
        __syncthreads();   // stage t free before t+2 load overwrites it
    }

    float il0 = 1.f / l0, il1 = 1.f / l1;
    int r0g = q0 + w*16 + g;
    __half* ob0 = o + (size_t)(b*SS + r0g) * HH + h * DD;
    __half* ob1 = ob0 + (size_t)8 * HH;
    #pragma unroll
    for (int ntl = 0; ntl < 16; ntl++) {
        int d = 8*ntl + 2*tig;
        __half2 v0 = __floats2half2_rn(oac[ntl][0]*il0, oac[ntl][1]*il0);
        __half2 v1 = __floats2half2_rn(oac[ntl][2]*il1, oac[ntl][3]*il1);
        *(__half2*)(ob0 + d) = v0;
        *(__half2*)(ob1 + d) = v1;
    }
}

// ================= silu(gate) * up (half out) =================
__global__ void silu_mul_kernel(const float* __restrict__ gu, __half* __restrict__ out) {
    int i = blockIdx.x * blockDim.x + threadIdx.x;
    int t = blockIdx.y;
    const float* row = gu + (size_t)t * GU_N;
    float g = row[i], u = row[II + i];
    out[(size_t)t * II + i] = __float2half_rn(g / (1.f + __expf(-g)) * u);
}

// ================= launch =================
extern "C" void kernel_launch(void* const* d_in, const int* in_sizes, int n_in,
                              void* d_out, int out_size) {
    const float* x     = (const float*)d_in[0];
    const float* cosT  = (const float*)d_in[1];
    const float* sinT  = (const float*)d_in[2];
    const float* anw   = (const float*)d_in[3];
    const float* fnw   = (const float*)d_in[4];
    const float* wq    = (const float*)d_in[5];
    const float* wk    = (const float*)d_in[6];
    const float* wv    = (const float*)d_in[7];
    const float* wo    = (const float*)d_in[8];
    const float* wgate = (const float*)d_in[9];
    const float* wup   = (const float*)d_in[10];
    const float* wdown = (const float*)d_in[11];
    float* out = (float*)d_out;

    __half *p_hin, *p_qh, *p_kh, *p_vt, *p_attn, *p_ffn, *p_wqkv, *p_wo, *p_wgu, *p_wd;
    float *p_qkv, *p_h, *p_gu;
    cudaGetSymbolAddress((void**)&p_hin,  g_hin);
    cudaGetSymbolAddress((void**)&p_qkv,  g_qkv);
    cudaGetSymbolAddress((void**)&p_qh,   g_qh);
    cudaGetSymbolAddress((void**)&p_kh,   g_kh);
    cudaGetSymbolAddress((void**)&p_vt,   g_vt);
    cudaGetSymbolAddress((void**)&p_attn, g_attn);
    cudaGetSymbolAddress((void**)&p_h,    g_h);
    cudaGetSymbolAddress((void**)&p_gu,   g_gu);
    cudaGetSymbolAddress((void**)&p_ffn,  g_ffn);
    cudaGetSymbolAddress((void**)&p_wqkv, g_wqkv);
    cudaGetSymbolAddress((void**)&p_wo,   g_wo_t);
    cudaGetSymbolAddress((void**)&p_wgu,  g_wgu);
    cudaGetSymbolAddress((void**)&p_wd,   g_wd_t);

    cudaFuncSetAttribute(hgemm<0>, cudaFuncAttributeMaxDynamicSharedMemorySize, SMEM_BYTES);
    cudaFuncSetAttribute(hgemm<1>, cudaFuncAttributeMaxDynamicSharedMemorySize, SMEM_BYTES);
    cudaFuncSetAttribute(fattn,    cudaFuncAttributeMaxDynamicSharedMemorySize, ATT_SMEM);

    dim3 tb(32, 8);
    pack_h_t<<<dim3(HH/32, HH/32), tb>>>(wq, p_wqkv, HH, HH);
    pack_h_t<<<dim3(HH/32, (NKV*DD)/32), tb>>>(wk, p_wqkv + (size_t)HH*HH, HH, NKV*DD);
    pack_h_t<<<dim3(HH/32, (NKV*DD)/32), tb>>>(wv, p_wqkv + (size_t)(HH+NKV*DD)*HH, HH, NKV*DD);
    pack_h_t<<<dim3(HH/32, HH/32), tb>>>(wo, p_wo, HH, HH);
    pack_h_t<<<dim3(HH/32, II/32), tb>>>(wgate, p_wgu, HH, II);
    pack_h_t<<<dim3(HH/32, II/32), tb>>>(wup,   p_wgu + (size_t)II*HH, HH, II);
    pack_h_t<<<dim3(II/32, HH/32), tb>>>(wdown, p_wd, II, HH);

    // 1) attn rmsnorm -> half
    rmsnorm_kernel<<<TT, 256>>>(x, anw, p_hin);

    // 2) fused qkv projection
    hgemm<0><<<dim3(TT/BM, QKV_N/BN), 256, SMEM_BYTES>>>(p_hin, p_wqkv, nullptr, p_qkv, TT, QKV_N, HH);

    // 3) RoPE + extract into attention layouts
    {
        int tq = TT * NQ * 64;
        rope_q<<<(tq + 255) / 256, 256>>>(p_qkv, cosT, sinT, p_qh);
        int tk = TT * NKV * 64;
        rope_k<<<(tk + 255) / 256, 256>>>(p_qkv, cosT, sinT, p_kh);
        v_trans<<<dim3(SS/32, DD/32, BB*NKV), tb>>>(p_qkv, p_vt);
    }

    // 4) flash attention -> half [b,s,h,d]
    fattn<<<dim3(SS/AQT, NQ, BB), 128, ATT_SMEM>>>(p_qh, p_kh, p_vt, p_attn);

    // 5) output projection + residual: h = x + attn @ wo
    hgemm<1><<<dim3(TT/BM, HH/BN), 256, SMEM_BYTES>>>(p_attn, p_wo, x, p_h, TT, HH, HH);

    // 6) ffn rmsnorm -> half
    rmsnorm_kernel<<<TT, 256>>>(p_h, fnw, p_hin);

    // 7) fused gate+up
    hgemm<0><<<dim3(TT/BM, GU_N/BN), 256, SMEM_BYTES>>>(p_hin, p_wgu, nullptr, p_gu, TT, GU_N, HH);

    // 8) silu(gate) * up -> half
    silu_mul_kernel<<<dim3(II/256, TT), 256>>>(p_gu, p_ffn);

    // 9) down projection + residual: out = h + ffn @ wdown
    hgemm<1><<<dim3(TT/BM, HH/BN), 256, SMEM_BYTES>>>(p_ffn, p_wd, p_h, out, TT, HH, II);
}